// round 1
// baseline (speedup 1.0000x reference)
#include <cuda_runtime.h>

#define H   256
#define KL  4
#define C   16
#define TMAX 8192
#define TB  32

// Scratch for per-tree child-summed hidden state (no dynamic allocation allowed).
__device__ float g_hsum[TMAX * H];

// ---------------------------------------------------------------------------
// Stage 1: per tree b
//   sdata[r][:] = x[leaf_idx[b][r]]                        (16 rows, 16 KB smem)
//   rolled[c][h] = sum_k sdata[(c-k)&15][:] @ Wz[k][:,h] + sum_k bz[k][h]
//   g_hsum[b][h] = sum_c elu(rolled[c][h])
// Thread h computes column h for all 16 children (acc in registers, smem reads
// are warp-broadcast -> conflict-free).
// ---------------------------------------------------------------------------
__global__ __launch_bounds__(256) void stage1_kernel(
    const float* __restrict__ x,
    const float* __restrict__ Wz,
    const float* __restrict__ bz,
    const int*   __restrict__ leaf_idx)
{
    __shared__ float sdata[C][H];

    const int b   = blockIdx.x;
    const int tid = threadIdx.x;

    // Gather the 16 leaf rows for this tree (coalesced per row).
    #pragma unroll
    for (int i = 0; i < (C * H) / 256; ++i) {
        int e   = tid + i * 256;
        int r   = e >> 8;        // row 0..15
        int col = e & (H - 1);   // col 0..255
        long src = (long)leaf_idx[b * C + r] * H + col;
        sdata[r][col] = x[src];
    }
    __syncthreads();

    const int h = tid;

    // Bias: every (t,c) gets sum_k bz[k][h].
    float bsum = bz[h] + bz[H + h] + bz[2 * H + h] + bz[3 * H + h];

    float acc[C];
    #pragma unroll
    for (int c = 0; c < C; ++c) acc[c] = bsum;

    // rolled_sum[c] = sum_k data[(c-k)&15] @ Wz[k]  ==  acc[(r+k)&15] += data[r]*Wz[k]
    #pragma unroll
    for (int k = 0; k < KL; ++k) {
        const float* __restrict__ wk = Wz + (size_t)k * H * H + h;
        #pragma unroll 4
        for (int j = 0; j < H; ++j) {
            float w = wk[(size_t)j * H];            // Wz[k][j][h], coalesced, L2-resident
            #pragma unroll
            for (int r = 0; r < C; ++r)
                acc[(r + k) & (C - 1)] += sdata[r][j] * w;  // compile-time reg index
        }
    }

    // ELU + sum over children (all thread-local).
    float s = 0.0f;
    #pragma unroll
    for (int c = 0; c < C; ++c) {
        float v = acc[c];
        s += (v > 0.0f) ? v : expm1f(v);
    }
    g_hsum[b * H + h] = s;
}

// ---------------------------------------------------------------------------
// Stage 2: out[t][h] = elu( g_hsum[t][:] @ Wzf[:,h] + C * bzf[h] )
// Block handles TB=32 trees; thread h owns column h for all 32 trees.
// ---------------------------------------------------------------------------
__global__ __launch_bounds__(256) void stage2_kernel(
    const float* __restrict__ Wzf,
    const float* __restrict__ bzf,
    float*       __restrict__ out,
    int T)
{
    __shared__ float sh[TB][H];

    const int b0  = blockIdx.x * TB;
    const int tid = threadIdx.x;

    #pragma unroll
    for (int i = 0; i < (TB * H) / 256; ++i) {
        int e   = tid + i * 256;
        int r   = e >> 8;
        int col = e & (H - 1);
        sh[r][col] = g_hsum[(b0 + r) * H + col];
    }
    __syncthreads();

    const int h = tid;

    float acc[TB];
    float binit = (float)C * bzf[h];
    #pragma unroll
    for (int r = 0; r < TB; ++r) acc[r] = binit;

    #pragma unroll 2
    for (int j = 0; j < H; ++j) {
        float w = Wzf[(size_t)j * H + h];           // coalesced, L2-resident
        #pragma unroll
        for (int r = 0; r < TB; ++r)
            acc[r] += sh[r][j] * w;
    }

    #pragma unroll
    for (int r = 0; r < TB; ++r) {
        float v = acc[r];
        out[(size_t)(b0 + r) * H + h] = (v > 0.0f) ? v : expm1f(v);
    }
}

// ---------------------------------------------------------------------------
// Launch. Input order (metadata): x, Wz, bz, Wzf, bzf, leaf_idx. Output fp32 [T,H].
// ---------------------------------------------------------------------------
extern "C" void kernel_launch(void* const* d_in, const int* in_sizes, int n_in,
                              void* d_out, int out_size)
{
    const float* x        = (const float*)d_in[0];
    const float* Wz       = (const float*)d_in[1];
    const float* bz       = (const float*)d_in[2];
    const float* Wzf      = (const float*)d_in[3];
    const float* bzf      = (const float*)d_in[4];
    const int*   leaf_idx = (const int*)  d_in[5];

    const int T = in_sizes[5] / C;   // 8192

    stage1_kernel<<<T, 256>>>(x, Wz, bz, leaf_idx);
    stage2_kernel<<<T / TB, 256>>>(Wzf, bzf, (float*)d_out, T);
}

// round 3
// speedup vs baseline: 2.8543x; 2.8543x over previous
#include <cuda_runtime.h>
#include <cuda_bf16.h>
#include <cstdint>

#define H    256
#define KL   4
#define C    16
#define TMAX 8192
#define TPB  8          // trees per block (= warps per block)

// ---------------------------------------------------------------------------
// Device scratch (no dynamic allocation allowed)
// ---------------------------------------------------------------------------
__device__ float g_hsum[TMAX * H];                 // 8 MB
__device__ __nv_bfloat16 g_Bhi[KL * H * H];        // Wz bf16 hi part, layout [k][h][d]
__device__ __nv_bfloat16 g_Blo[KL * H * H];        // lo part

// ---------------------------------------------------------------------------
// SMEM layout (dynamic). Padded strides -> conflict-free ldmatrix.
//   A row stride: 264 bf16 = 528 B  (528 mod 128 = 16 -> 8 rows hit 8 banksets)
//   B row stride:  72 bf16 = 144 B  (144 mod 128 = 16 -> same property)
// ---------------------------------------------------------------------------
#define OFF_BIAS   0
#define OFF_A_HI   1024
#define A_ROW_B    528
#define A_TREE_B   (16 * A_ROW_B)                  // 8448
#define A_TOTAL    (TPB * A_TREE_B)                // 67584
#define OFF_A_LO   (OFF_A_HI + A_TOTAL)
#define OFF_B      (OFF_A_LO + A_TOTAL)            // 136192
#define B_ROW_B    144
#define B_TERM_B   (16 * B_ROW_B)                  // 2304
#define B_CHUNK_B  (2 * B_TERM_B)                  // 4608 (hi + lo)
#define SMEM_TOTAL (OFF_B + 2 * B_CHUNK_B)         // 145408

// ---------------------------------------------------------------------------
// Helpers
// ---------------------------------------------------------------------------
__device__ __forceinline__ uint32_t smem_u32(const void* p) {
    uint32_t a;
    asm("{ .reg .u64 t; cvta.to.shared.u64 t, %1; cvt.u32.u64 %0, t; }" : "=r"(a) : "l"(p));
    return a;
}
__device__ __forceinline__ void cp16(uint32_t dst, const void* src) {
    uint64_t g;
    asm("cvta.to.global.u64 %0, %1;" : "=l"(g) : "l"(src));
    asm volatile("cp.async.cg.shared.global [%0], [%1], 16;" :: "r"(dst), "l"(g));
}
__device__ __forceinline__ void ldsm_x4(uint32_t (&r)[4], uint32_t addr) {
    asm volatile("ldmatrix.sync.aligned.m8n8.x4.shared.b16 {%0,%1,%2,%3}, [%4];"
                 : "=r"(r[0]), "=r"(r[1]), "=r"(r[2]), "=r"(r[3]) : "r"(addr));
}
__device__ __forceinline__ void ldsm_x2t(uint32_t (&r)[2], uint32_t addr) {
    asm volatile("ldmatrix.sync.aligned.m8n8.x2.trans.shared.b16 {%0,%1}, [%2];"
                 : "=r"(r[0]), "=r"(r[1]) : "r"(addr));
}
__device__ __forceinline__ void mma16816(float (&c)[4], const uint32_t (&a)[4],
                                         const uint32_t (&b)[2]) {
    asm volatile(
        "mma.sync.aligned.m16n8k16.row.col.f32.bf16.bf16.f32 "
        "{%0,%1,%2,%3}, {%4,%5,%6,%7}, {%8,%9}, {%0,%1,%2,%3};"
        : "+f"(c[0]), "+f"(c[1]), "+f"(c[2]), "+f"(c[3])
        : "r"(a[0]), "r"(a[1]), "r"(a[2]), "r"(a[3]), "r"(b[0]), "r"(b[1]));
}
__device__ __forceinline__ float elu(float v) { return (v > 0.0f) ? v : expm1f(v); }

// ---------------------------------------------------------------------------
// Prep: elementwise bf16 hi/lo split of Wz (layout unchanged: [k][h][d])
// ---------------------------------------------------------------------------
__global__ void prep_kernel(const float* __restrict__ Wz) {
    int idx = blockIdx.x * 256 + threadIdx.x;
    float v = Wz[idx];
    __nv_bfloat16 hi = __float2bfloat16_rn(v);
    g_Bhi[idx] = hi;
    g_Blo[idx] = __float2bfloat16_rn(v - __bfloat162float(hi));
}

// ---------------------------------------------------------------------------
// Stage 1: warp w owns tree blk*8+w. A = gathered leaves (16 x 256), hi/lo bf16.
// Accumulate sum_k roll_k(data) @ Wz[k] via per-lane row-permuted ldmatrix.
// 3 split products into one fp32 accumulator. Epilogue: +bias, ELU, 16-row sum.
// ---------------------------------------------------------------------------
__global__ __launch_bounds__(256, 1) void stage1_kernel(
    const float* __restrict__ x,
    const float* __restrict__ bz,
    const int*   __restrict__ leaf_idx)
{
    extern __shared__ char smem[];
    const uint32_t sb = smem_u32(smem);
    const int tid = threadIdx.x, wid = tid >> 5, lane = tid & 31;
    const int blk = blockIdx.x;

    // bias[d] = sum_k bz[k][d]
    ((float*)(smem + OFF_BIAS))[tid] = bz[tid] + bz[H + tid] + bz[2 * H + tid] + bz[3 * H + tid];

    // Gather A: 128 rows (8 trees x 16 children); 2 threads/row, 128 cols each.
    {
        int row = tid >> 1, half = tid & 1;
        int tree = blk * TPB + (row >> 4);
        int child = row & 15;
        int leaf = leaf_idx[tree * C + child];
        const float4* src = (const float4*)(x + (size_t)leaf * H + half * 128);
        char* dhi = smem + OFF_A_HI + (row >> 4) * A_TREE_B + child * A_ROW_B + half * 256;
        char* dlo = dhi + (OFF_A_LO - OFF_A_HI);
        #pragma unroll
        for (int g = 0; g < 16; ++g) {
            float4 v0 = src[2 * g], v1 = src[2 * g + 1];
            float f[8] = {v0.x, v0.y, v0.z, v0.w, v1.x, v1.y, v1.z, v1.w};
            uint32_t hw[4], lw[4];
            #pragma unroll
            for (int p = 0; p < 4; ++p) {
                __nv_bfloat16 ha = __float2bfloat16_rn(f[2 * p]);
                __nv_bfloat16 hb = __float2bfloat16_rn(f[2 * p + 1]);
                __nv_bfloat16 la = __float2bfloat16_rn(f[2 * p]     - __bfloat162float(ha));
                __nv_bfloat16 lb = __float2bfloat16_rn(f[2 * p + 1] - __bfloat162float(hb));
                __nv_bfloat162 hv; hv.x = ha; hv.y = hb;
                __nv_bfloat162 lv; lv.x = la; lv.y = lb;
                hw[p] = *reinterpret_cast<uint32_t*>(&hv);
                lw[p] = *reinterpret_cast<uint32_t*>(&lv);
            }
            *(uint4*)(dhi + g * 16) = make_uint4(hw[0], hw[1], hw[2], hw[3]);
            *(uint4*)(dlo + g * 16) = make_uint4(lw[0], lw[1], lw[2], lw[3]);
        }
    }
    __syncthreads();

    const uint32_t aHi   = sb + OFF_A_HI + wid * A_TREE_B;
    const int rowlog     = lane & 15;        // logical child row for A frag
    const int khalf      = lane >> 4;        // k-halves 0-7 / 8-15
    // B-copy mapping: 256 threads == 2 terms x 16 rows x 8 vec16
    const int bterm = tid >> 7, brow = (tid >> 3) & 15, bv8 = (tid & 7) * 8;
    const __nv_bfloat16* bsrc = bterm ? g_Blo : g_Bhi;
    const int tree = blk * TPB + wid;
    const float* bias = (const float*)(smem + OFF_BIAS);

    #pragma unroll 1
    for (int nc = 0; nc < 4; ++nc) {
        float acc[8][4];
        #pragma unroll
        for (int nt = 0; nt < 8; ++nt)
            #pragma unroll
            for (int j = 0; j < 4; ++j) acc[nt][j] = 0.0f;

        // prime chunk 0 (kl=0, ks=0)
        cp16(sb + OFF_B + bterm * B_TERM_B + brow * B_ROW_B + bv8 * 2,
             bsrc + brow * 256 + nc * 64 + bv8);
        asm volatile("cp.async.commit_group;");

        #pragma unroll 1
        for (int t64 = 0; t64 < 64; ++t64) {
            const int buf = t64 & 1;
            if (t64 < 63) {
                int nx = t64 + 1, kl2 = nx >> 4, ks2 = nx & 15;
                cp16(sb + OFF_B + (buf ^ 1) * B_CHUNK_B + bterm * B_TERM_B + brow * B_ROW_B + bv8 * 2,
                     bsrc + kl2 * 65536 + (ks2 * 16 + brow) * 256 + nc * 64 + bv8);
                asm volatile("cp.async.commit_group;");
                asm volatile("cp.async.wait_group 1;");
            } else {
                asm volatile("cp.async.wait_group 0;");
            }
            __syncthreads();

            const int kl = t64 >> 4, ks = t64 & 15;
            const int rowp = (rowlog - kl) & 15;            // bake the roll into A rows
            const uint32_t aAddr = aHi + rowp * A_ROW_B + (ks * 2 + khalf) * 16;

            uint32_t ah[4], al[4];
            ldsm_x4(ah, aAddr);
            ldsm_x4(al, aAddr + A_TOTAL);

            const uint32_t bbase = sb + OFF_B + buf * B_CHUNK_B + (lane & 15) * B_ROW_B;
            uint32_t bh[8][2], bl[8][2];
            #pragma unroll
            for (int nt = 0; nt < 8; ++nt) {
                ldsm_x2t(bh[nt], bbase + nt * 16);
                ldsm_x2t(bl[nt], bbase + B_TERM_B + nt * 16);
            }
            #pragma unroll
            for (int nt = 0; nt < 8; ++nt) mma16816(acc[nt], ah, bh[nt]);
            #pragma unroll
            for (int nt = 0; nt < 8; ++nt) mma16816(acc[nt], al, bh[nt]);
            #pragma unroll
            for (int nt = 0; nt < 8; ++nt) mma16816(acc[nt], ah, bl[nt]);

            __syncthreads();
        }

        // Epilogue: +bias, ELU, sum over the 16 children rows, store 64 cols.
        #pragma unroll
        for (int nt = 0; nt < 8; ++nt) {
            int col = nc * 64 + nt * 8 + (lane & 3) * 2;
            float b0 = bias[col], b1 = bias[col + 1];
            float v00 = elu(acc[nt][0] + b0);
            float v01 = elu(acc[nt][1] + b1);
            float v10 = elu(acc[nt][2] + b0);
            float v11 = elu(acc[nt][3] + b1);
            float s0 = v00 + v10;   // rows g and g+8 (same column)
            float s1 = v01 + v11;
            #pragma unroll
            for (int sh = 4; sh <= 16; sh <<= 1) {
                s0 += __shfl_xor_sync(0xffffffffu, s0, sh);
                s1 += __shfl_xor_sync(0xffffffffu, s1, sh);
            }
            if (lane < 4) {
                g_hsum[(size_t)tree * H + col]     = s0;
                g_hsum[(size_t)tree * H + col + 1] = s1;
            }
        }
    }
}

// ---------------------------------------------------------------------------
// Stage 2: out[t][h] = elu( g_hsum[t][:] @ Wzf[:,h] + C * bzf[h] )
// ---------------------------------------------------------------------------
#define TB2 16
__global__ __launch_bounds__(256) void stage2_kernel(
    const float* __restrict__ Wzf,
    const float* __restrict__ bzf,
    float*       __restrict__ out)
{
    __shared__ float sh[TB2][H];
    const int b0 = blockIdx.x * TB2;
    const int tid = threadIdx.x;

    #pragma unroll
    for (int i = 0; i < (TB2 * H) / 256; ++i) {
        int e = tid + i * 256;
        sh[e >> 8][e & (H - 1)] = g_hsum[(size_t)(b0 + (e >> 8)) * H + (e & (H - 1))];
    }
    __syncthreads();

    const int h = tid;
    float acc[TB2];
    float binit = (float)C * bzf[h];
    #pragma unroll
    for (int r = 0; r < TB2; ++r) acc[r] = binit;

    #pragma unroll 4
    for (int j = 0; j < H; ++j) {
        float w = Wzf[(size_t)j * H + h];
        #pragma unroll
        for (int r = 0; r < TB2; ++r) acc[r] += sh[r][j] * w;
    }

    #pragma unroll
    for (int r = 0; r < TB2; ++r)
        out[(size_t)(b0 + r) * H + h] = elu(acc[r]);
}

// ---------------------------------------------------------------------------
// Launch: prep -> stage1 (mma.sync bf16x3) -> stage2
// ---------------------------------------------------------------------------
extern "C" void kernel_launch(void* const* d_in, const int* in_sizes, int n_in,
                              void* d_out, int out_size)
{
    const float* x        = (const float*)d_in[0];
    const float* Wz       = (const float*)d_in[1];
    const float* bz       = (const float*)d_in[2];
    const float* Wzf      = (const float*)d_in[3];
    const float* bzf      = (const float*)d_in[4];
    const int*   leaf_idx = (const int*)  d_in[5];

    const int T = in_sizes[5] / C;   // 8192

    cudaFuncSetAttribute(stage1_kernel,
                         cudaFuncAttributeMaxDynamicSharedMemorySize, SMEM_TOTAL);

    prep_kernel<<<KL * H * H / 256, 256>>>(Wz);
    stage1_kernel<<<T / TPB, 256, SMEM_TOTAL>>>(x, bz, leaf_idx);
    stage2_kernel<<<T / TB2, 256>>>(Wzf, bzf, (float*)d_out);
}

// round 4
// speedup vs baseline: 3.1116x; 1.0901x over previous
#include <cuda_runtime.h>
#include <cuda_bf16.h>
#include <cstdint>

#define H    256
#define KL   4
#define C    16
#define TMAX 8192
#define TPB  8          // trees per block (= warps per block)

// ---------------------------------------------------------------------------
// Device scratch (no dynamic allocation allowed)
// ---------------------------------------------------------------------------
__device__ float g_hsum[TMAX * H];                 // 8 MB
__device__ __nv_bfloat16 g_Bhi[KL * H * H];        // Wz bf16 hi part, layout [k][h][d]
__device__ __nv_bfloat16 g_Blo[KL * H * H];        // lo part

// ---------------------------------------------------------------------------
// SMEM layout. Padded strides -> conflict-free ldmatrix.
//   A row stride: 528 B  (528 mod 128 = 16 -> 8 rows hit 8 distinct phases)
//   B row stride: 144 B  (same property)
// ---------------------------------------------------------------------------
#define OFF_BIAS   0
#define OFF_A_HI   1024
#define A_ROW_B    528
#define A_TREE_B   (16 * A_ROW_B)                  // 8448
#define A_TOTAL    (TPB * A_TREE_B)                // 67584
#define OFF_A_LO   (OFF_A_HI + A_TOTAL)
#define OFF_B      (OFF_A_LO + A_TOTAL)            // 136192
#define B_ROW_B    144
#define B_SUB_B    (16 * B_ROW_B)                  // 2304  (one k-step, one term)
#define B_TERM_B   (2 * B_SUB_B)                   // 4608  (two k-steps, one term)
#define B_STAGE_B  (2 * B_TERM_B)                  // 9216  (hi + lo)
#define NSTAGE     3
#define SMEM_TOTAL (OFF_B + NSTAGE * B_STAGE_B)    // 163840

// ---------------------------------------------------------------------------
// Helpers
// ---------------------------------------------------------------------------
__device__ __forceinline__ uint32_t smem_u32(const void* p) {
    uint32_t a;
    asm("{ .reg .u64 t; cvta.to.shared.u64 t, %1; cvt.u32.u64 %0, t; }" : "=r"(a) : "l"(p));
    return a;
}
__device__ __forceinline__ void cp16(uint32_t dst, const void* src) {
    uint64_t g;
    asm("cvta.to.global.u64 %0, %1;" : "=l"(g) : "l"(src));
    asm volatile("cp.async.cg.shared.global [%0], [%1], 16;" :: "r"(dst), "l"(g));
}
__device__ __forceinline__ void ldsm_x4(uint32_t (&r)[4], uint32_t addr) {
    asm volatile("ldmatrix.sync.aligned.m8n8.x4.shared.b16 {%0,%1,%2,%3}, [%4];"
                 : "=r"(r[0]), "=r"(r[1]), "=r"(r[2]), "=r"(r[3]) : "r"(addr));
}
__device__ __forceinline__ void ldsm_x4t(uint32_t (&r)[4], uint32_t addr) {
    asm volatile("ldmatrix.sync.aligned.m8n8.x4.trans.shared.b16 {%0,%1,%2,%3}, [%4];"
                 : "=r"(r[0]), "=r"(r[1]), "=r"(r[2]), "=r"(r[3]) : "r"(addr));
}
__device__ __forceinline__ void mma16816(float (&c)[4], const uint32_t (&a)[4],
                                         uint32_t b0, uint32_t b1) {
    asm volatile(
        "mma.sync.aligned.m16n8k16.row.col.f32.bf16.bf16.f32 "
        "{%0,%1,%2,%3}, {%4,%5,%6,%7}, {%8,%9}, {%0,%1,%2,%3};"
        : "+f"(c[0]), "+f"(c[1]), "+f"(c[2]), "+f"(c[3])
        : "r"(a[0]), "r"(a[1]), "r"(a[2]), "r"(a[3]), "r"(b0), "r"(b1));
}
__device__ __forceinline__ float elu(float v) { return (v > 0.0f) ? v : expm1f(v); }

// Copy one B stage: 2 k-steps (32 h-rows x 64 d-cols), hi + lo. 512 cp16 total.
__device__ __forceinline__ void copyB(uint32_t dstStage, int nc, int kp, int tid) {
    const int kl = kp >> 3;
    const int h0 = (kp & 7) * 32;
    #pragma unroll
    for (int i = 0; i < 2; ++i) {
        int idx  = tid + i * 256;            // 0..511
        int term = idx >> 8;                 // 0 = hi, 1 = lo
        int r    = (idx >> 3) & 31;          // 0..31
        int v8   = (idx & 7) * 8;            // 0..56
        const __nv_bfloat16* src =
            (term ? g_Blo : g_Bhi) + (size_t)kl * 65536 + (size_t)(h0 + r) * 256 + nc * 64 + v8;
        cp16(dstStage + term * B_TERM_B + r * B_ROW_B + v8 * 2, src);
    }
}

// ---------------------------------------------------------------------------
// Prep: elementwise bf16 hi/lo split of Wz (layout unchanged: [k][h][d])
// ---------------------------------------------------------------------------
__global__ void prep_kernel(const float* __restrict__ Wz) {
    int idx = blockIdx.x * 256 + threadIdx.x;
    float v = Wz[idx];
    __nv_bfloat16 hi = __float2bfloat16_rn(v);
    g_Bhi[idx] = hi;
    g_Blo[idx] = __float2bfloat16_rn(v - __bfloat162float(hi));
}

// ---------------------------------------------------------------------------
// Stage 1: warp w owns tree blk*8+w. Accumulate sum_k roll_k(data) @ Wz[k]
// via per-lane row-permuted ldmatrix A addressing. 3-term bf16 split.
// Flattened 128-iteration pipeline: iter = (nc, 2 k-steps); 3-stage cp.async
// ring, ONE __syncthreads per iteration; B fragments via ldmatrix.x4.trans.
// ---------------------------------------------------------------------------
__global__ __launch_bounds__(256, 1) void stage1_kernel(
    const float* __restrict__ x,
    const float* __restrict__ bz,
    const int*   __restrict__ leaf_idx)
{
    extern __shared__ char smem[];
    const uint32_t sb = smem_u32(smem);
    const int tid = threadIdx.x, wid = tid >> 5, lane = tid & 31;
    const int blk = blockIdx.x;

    // bias[d] = sum_k bz[k][d]
    ((float*)(smem + OFF_BIAS))[tid] = bz[tid] + bz[H + tid] + bz[2 * H + tid] + bz[3 * H + tid];

    // Gather A: 128 rows (8 trees x 16 children); 2 threads/row, 128 cols each.
    {
        int row = tid >> 1, half = tid & 1;
        int tree = blk * TPB + (row >> 4);
        int child = row & 15;
        int leaf = leaf_idx[tree * C + child];
        const float4* src = (const float4*)(x + (size_t)leaf * H + half * 128);
        char* dhi = smem + OFF_A_HI + (row >> 4) * A_TREE_B + child * A_ROW_B + half * 256;
        char* dlo = dhi + (OFF_A_LO - OFF_A_HI);
        #pragma unroll
        for (int g = 0; g < 16; ++g) {
            float4 v0 = src[2 * g], v1 = src[2 * g + 1];
            float f[8] = {v0.x, v0.y, v0.z, v0.w, v1.x, v1.y, v1.z, v1.w};
            uint32_t hw[4], lw[4];
            #pragma unroll
            for (int p = 0; p < 4; ++p) {
                __nv_bfloat16 ha = __float2bfloat16_rn(f[2 * p]);
                __nv_bfloat16 hb = __float2bfloat16_rn(f[2 * p + 1]);
                __nv_bfloat16 la = __float2bfloat16_rn(f[2 * p]     - __bfloat162float(ha));
                __nv_bfloat16 lb = __float2bfloat16_rn(f[2 * p + 1] - __bfloat162float(hb));
                __nv_bfloat162 hv; hv.x = ha; hv.y = hb;
                __nv_bfloat162 lv; lv.x = la; lv.y = lb;
                hw[p] = *reinterpret_cast<uint32_t*>(&hv);
                lw[p] = *reinterpret_cast<uint32_t*>(&lv);
            }
            *(uint4*)(dhi + g * 16) = make_uint4(hw[0], hw[1], hw[2], hw[3]);
            *(uint4*)(dlo + g * 16) = make_uint4(lw[0], lw[1], lw[2], lw[3]);
        }
    }

    // Prime first two pipeline stages (iters 0, 1).
    copyB(sb + OFF_B + 0 * B_STAGE_B, 0, 0, tid);
    asm volatile("cp.async.commit_group;");
    copyB(sb + OFF_B + 1 * B_STAGE_B, 0, 1, tid);
    asm volatile("cp.async.commit_group;");

    __syncthreads();   // A gather visible to all warps

    const uint32_t aHi = sb + OFF_A_HI + wid * A_TREE_B;
    const int rowlog   = lane & 15;
    const int khalf    = lane >> 4;
    const int tree     = blk * TPB + wid;
    const float* bias  = (const float*)(smem + OFF_BIAS);

    float acc[8][4];

    #pragma unroll 1
    for (int it = 0; it < 128; ++it) {
        const int nc = it >> 5, kp = it & 31, kl = kp >> 3;

        if (kp == 0) {
            #pragma unroll
            for (int nt = 0; nt < 8; ++nt)
                #pragma unroll
                for (int j = 0; j < 4; ++j) acc[nt][j] = 0.0f;
        }

        // Pipeline: ensure this iter's stage is resident; prefetch iter+2.
        if (it + 2 < 128) {
            asm volatile("cp.async.wait_group 1;");
            __syncthreads();
            const int nit = it + 2;
            copyB(sb + OFF_B + (nit % NSTAGE) * B_STAGE_B, nit >> 5, nit & 31, tid);
            asm volatile("cp.async.commit_group;");
        } else {
            asm volatile("cp.async.wait_group 0;");
            __syncthreads();
        }

        const uint32_t stg = sb + OFF_B + (it % NSTAGE) * B_STAGE_B;
        const int rowp = (rowlog - kl) & 15;              // roll baked into A rows
        const uint32_t aRow = aHi + rowp * A_ROW_B + khalf * 16;

        #pragma unroll
        for (int s = 0; s < 2; ++s) {                     // two k-steps per stage
            const int ks = (kp & 7) * 2 + s;
            const uint32_t aAddr = aRow + ks * 32;

            uint32_t ah[4], al[4];
            ldsm_x4(ah, aAddr);
            ldsm_x4(al, aAddr + A_TOTAL);

            const uint32_t bbH = stg + s * B_SUB_B + (lane & 15) * B_ROW_B + khalf * 16;
            #pragma unroll
            for (int p = 0; p < 4; ++p) {                 // nt pairs (2p, 2p+1)
                uint32_t bh[4], bl[4];
                ldsm_x4t(bh, bbH + p * 32);
                ldsm_x4t(bl, bbH + B_TERM_B + p * 32);
                mma16816(acc[2 * p],     ah, bh[0], bh[1]);
                mma16816(acc[2 * p + 1], ah, bh[2], bh[3]);
                mma16816(acc[2 * p],     al, bh[0], bh[1]);
                mma16816(acc[2 * p + 1], al, bh[2], bh[3]);
                mma16816(acc[2 * p],     ah, bl[0], bl[1]);
                mma16816(acc[2 * p + 1], ah, bl[2], bl[3]);
            }
        }

        // Epilogue at the end of each nc: +bias, ELU, 16-child reduce, store.
        if (kp == 31) {
            #pragma unroll
            for (int nt = 0; nt < 8; ++nt) {
                int col = nc * 64 + nt * 8 + (lane & 3) * 2;
                float b0 = bias[col], b1 = bias[col + 1];
                float s0 = elu(acc[nt][0] + b0) + elu(acc[nt][2] + b0);
                float s1 = elu(acc[nt][1] + b1) + elu(acc[nt][3] + b1);
                #pragma unroll
                for (int sh = 4; sh <= 16; sh <<= 1) {
                    s0 += __shfl_xor_sync(0xffffffffu, s0, sh);
                    s1 += __shfl_xor_sync(0xffffffffu, s1, sh);
                }
                if (lane < 4) {
                    g_hsum[(size_t)tree * H + col]     = s0;
                    g_hsum[(size_t)tree * H + col + 1] = s1;
                }
            }
        }
    }
}

// ---------------------------------------------------------------------------
// Stage 2: out[t][h] = elu( g_hsum[t][:] @ Wzf[:,h] + C * bzf[h] )
// ---------------------------------------------------------------------------
#define TB2 16
__global__ __launch_bounds__(256) void stage2_kernel(
    const float* __restrict__ Wzf,
    const float* __restrict__ bzf,
    float*       __restrict__ out)
{
    __shared__ float sh[TB2][H];
    const int b0 = blockIdx.x * TB2;
    const int tid = threadIdx.x;

    #pragma unroll
    for (int i = 0; i < (TB2 * H) / 256; ++i) {
        int e = tid + i * 256;
        sh[e >> 8][e & (H - 1)] = g_hsum[(size_t)(b0 + (e >> 8)) * H + (e & (H - 1))];
    }
    __syncthreads();

    const int h = tid;
    float acc[TB2];
    float binit = (float)C * bzf[h];
    #pragma unroll
    for (int r = 0; r < TB2; ++r) acc[r] = binit;

    #pragma unroll 4
    for (int j = 0; j < H; ++j) {
        float w = Wzf[(size_t)j * H + h];
        #pragma unroll
        for (int r = 0; r < TB2; ++r) acc[r] += sh[r][j] * w;
    }

    #pragma unroll
    for (int r = 0; r < TB2; ++r)
        out[(size_t)(b0 + r) * H + h] = elu(acc[r]);
}

// ---------------------------------------------------------------------------
// Launch: prep -> stage1 (mma.sync bf16x3, pipelined) -> stage2
// ---------------------------------------------------------------------------
extern "C" void kernel_launch(void* const* d_in, const int* in_sizes, int n_in,
                              void* d_out, int out_size)
{
    const float* x        = (const float*)d_in[0];
    const float* Wz       = (const float*)d_in[1];
    const float* bz       = (const float*)d_in[2];
    const float* Wzf      = (const float*)d_in[3];
    const float* bzf      = (const float*)d_in[4];
    const int*   leaf_idx = (const int*)  d_in[5];

    const int T = in_sizes[5] / C;   // 8192

    cudaFuncSetAttribute(stage1_kernel,
                         cudaFuncAttributeMaxDynamicSharedMemorySize, SMEM_TOTAL);

    prep_kernel<<<KL * H * H / 256, 256>>>(Wz);
    stage1_kernel<<<T / TPB, 256, SMEM_TOTAL>>>(x, bz, leaf_idx);
    stage2_kernel<<<T / TB2, 256>>>(Wzf, bzf, (float*)d_out);
}

// round 5
// speedup vs baseline: 6.1201x; 1.9669x over previous
#include <cuda_runtime.h>
#include <cuda_fp16.h>
#include <cstdint>

#define H    256
#define KL   4
#define C    16
#define TMAX 8192
#define TPB  8          // trees per block (= warps per block)

// ---------------------------------------------------------------------------
// Device scratch (no dynamic allocation allowed)
// ---------------------------------------------------------------------------
__device__ float  g_hsum[TMAX * H];          // 8 MB
__device__ __half g_Bh[KL * H * H];          // Wz in fp16, layout [k][h][d]

// ---------------------------------------------------------------------------
// SMEM layout. Padded strides -> conflict-free ldmatrix.
//   A row stride: 528 B  (528 mod 128 = 16 -> 8 rows hit 8 distinct phases)
//   B row stride: 144 B  (same property)
// ---------------------------------------------------------------------------
#define OFF_BIAS   0
#define OFF_A      1024
#define A_ROW_B    528
#define A_TREE_B   (16 * A_ROW_B)                  // 8448
#define A_TOTAL    (TPB * A_TREE_B)                // 67584
#define OFF_B      (OFF_A + A_TOTAL)               // 68608
#define B_ROW_B    144
#define B_SUB_B    (16 * B_ROW_B)                  // 2304  (one k-step)
#define B_STAGE_B  (2 * B_SUB_B)                   // 4608  (two k-steps)
#define NSTAGE     3
#define SMEM_TOTAL (OFF_B + NSTAGE * B_STAGE_B)    // 82432 -> 2 blocks/SM

// ---------------------------------------------------------------------------
// Helpers
// ---------------------------------------------------------------------------
__device__ __forceinline__ uint32_t smem_u32(const void* p) {
    uint32_t a;
    asm("{ .reg .u64 t; cvta.to.shared.u64 t, %1; cvt.u32.u64 %0, t; }" : "=r"(a) : "l"(p));
    return a;
}
__device__ __forceinline__ void cp16(uint32_t dst, const void* src) {
    uint64_t g;
    asm("cvta.to.global.u64 %0, %1;" : "=l"(g) : "l"(src));
    asm volatile("cp.async.cg.shared.global [%0], [%1], 16;" :: "r"(dst), "l"(g));
}
__device__ __forceinline__ void ldsm_x4(uint32_t (&r)[4], uint32_t addr) {
    asm volatile("ldmatrix.sync.aligned.m8n8.x4.shared.b16 {%0,%1,%2,%3}, [%4];"
                 : "=r"(r[0]), "=r"(r[1]), "=r"(r[2]), "=r"(r[3]) : "r"(addr));
}
__device__ __forceinline__ void ldsm_x4t(uint32_t (&r)[4], uint32_t addr) {
    asm volatile("ldmatrix.sync.aligned.m8n8.x4.trans.shared.b16 {%0,%1,%2,%3}, [%4];"
                 : "=r"(r[0]), "=r"(r[1]), "=r"(r[2]), "=r"(r[3]) : "r"(addr));
}
__device__ __forceinline__ void mma16816(float (&c)[4], const uint32_t (&a)[4],
                                         uint32_t b0, uint32_t b1) {
    asm volatile(
        "mma.sync.aligned.m16n8k16.row.col.f32.f16.f16.f32 "
        "{%0,%1,%2,%3}, {%4,%5,%6,%7}, {%8,%9}, {%0,%1,%2,%3};"
        : "+f"(c[0]), "+f"(c[1]), "+f"(c[2]), "+f"(c[3])
        : "r"(a[0]), "r"(a[1]), "r"(a[2]), "r"(a[3]), "r"(b0), "r"(b1));
}
__device__ __forceinline__ float elu(float v) { return (v > 0.0f) ? v : expm1f(v); }

// Copy one B stage: 2 k-steps = 32 h-rows x 64 d-cols fp16. 256 cp16 = 1/thread.
__device__ __forceinline__ void copyB(uint32_t dstStage, int nc, int kp, int tid) {
    const int kl = kp >> 3;
    const int h0 = (kp & 7) * 32;
    const int r  = tid >> 3;             // 0..31
    const int v8 = (tid & 7) * 8;        // 0..56
    const __half* src = g_Bh + (size_t)kl * 65536 + (size_t)(h0 + r) * 256 + nc * 64 + v8;
    cp16(dstStage + r * B_ROW_B + v8 * 2, src);
}

// ---------------------------------------------------------------------------
// Prep: Wz -> fp16 (layout unchanged: [k][h][d])
// ---------------------------------------------------------------------------
__global__ void prep_kernel(const float* __restrict__ Wz) {
    int idx = blockIdx.x * 256 + threadIdx.x;
    g_Bh[idx] = __float2half_rn(Wz[idx]);
}

// ---------------------------------------------------------------------------
// Stage 1: warp w owns tree blk*8+w. Accumulate sum_k roll_k(data) @ Wz[k]
// via per-lane row-permuted ldmatrix A addressing, single fp16 product.
// Flattened 128-iteration pipeline: iter = (nc, 2 k-steps); 3-stage cp.async
// ring, ONE __syncthreads per iteration.
// ---------------------------------------------------------------------------
__global__ __launch_bounds__(256, 2) void stage1_kernel(
    const float* __restrict__ x,
    const float* __restrict__ bz,
    const int*   __restrict__ leaf_idx)
{
    extern __shared__ char smem[];
    const uint32_t sb = smem_u32(smem);
    const int tid = threadIdx.x, wid = tid >> 5, lane = tid & 31;
    const int blk = blockIdx.x;

    // bias[d] = sum_k bz[k][d]
    ((float*)(smem + OFF_BIAS))[tid] = bz[tid] + bz[H + tid] + bz[2 * H + tid] + bz[3 * H + tid];

    // Gather A: 128 rows (8 trees x 16 children) -> fp16; 2 threads/row.
    {
        int row = tid >> 1, half = tid & 1;
        int tree = blk * TPB + (row >> 4);
        int child = row & 15;
        int leaf = leaf_idx[tree * C + child];
        const float4* src = (const float4*)(x + (size_t)leaf * H + half * 128);
        char* dst = smem + OFF_A + (row >> 4) * A_TREE_B + child * A_ROW_B + half * 256;
        #pragma unroll
        for (int g = 0; g < 16; ++g) {
            float4 v0 = src[2 * g], v1 = src[2 * g + 1];
            __half2 h0 = __floats2half2_rn(v0.x, v0.y);
            __half2 h1 = __floats2half2_rn(v0.z, v0.w);
            __half2 h2 = __floats2half2_rn(v1.x, v1.y);
            __half2 h3 = __floats2half2_rn(v1.z, v1.w);
            *(uint4*)(dst + g * 16) = make_uint4(
                *reinterpret_cast<uint32_t*>(&h0), *reinterpret_cast<uint32_t*>(&h1),
                *reinterpret_cast<uint32_t*>(&h2), *reinterpret_cast<uint32_t*>(&h3));
        }
    }

    // Prime first two pipeline stages (iters 0, 1).
    copyB(sb + OFF_B + 0 * B_STAGE_B, 0, 0, tid);
    asm volatile("cp.async.commit_group;");
    copyB(sb + OFF_B + 1 * B_STAGE_B, 0, 1, tid);
    asm volatile("cp.async.commit_group;");

    __syncthreads();   // A gather visible to all warps

    const uint32_t aBase = sb + OFF_A + wid * A_TREE_B;
    const int rowlog   = lane & 15;
    const int khalf    = lane >> 4;
    const int tree     = blk * TPB + wid;
    const float* bias  = (const float*)(smem + OFF_BIAS);

    float acc[8][4];

    #pragma unroll 1
    for (int it = 0; it < 128; ++it) {
        const int nc = it >> 5, kp = it & 31, kl = kp >> 3;

        if (kp == 0) {
            #pragma unroll
            for (int nt = 0; nt < 8; ++nt)
                #pragma unroll
                for (int j = 0; j < 4; ++j) acc[nt][j] = 0.0f;
        }

        // Pipeline: ensure this iter's stage is resident; prefetch iter+2.
        if (it + 2 < 128) {
            asm volatile("cp.async.wait_group 1;");
            __syncthreads();
            const int nit = it + 2;
            copyB(sb + OFF_B + (nit % NSTAGE) * B_STAGE_B, nit >> 5, nit & 31, tid);
            asm volatile("cp.async.commit_group;");
        } else {
            asm volatile("cp.async.wait_group 0;");
            __syncthreads();
        }

        const uint32_t stg = sb + OFF_B + (it % NSTAGE) * B_STAGE_B;
        const int rowp = (rowlog - kl) & 15;              // roll baked into A rows
        const uint32_t aRow = aBase + rowp * A_ROW_B + khalf * 16;

        #pragma unroll
        for (int s = 0; s < 2; ++s) {                     // two k-steps per stage
            const int ks = (kp & 7) * 2 + s;

            uint32_t a[4];
            ldsm_x4(a, aRow + ks * 32);

            const uint32_t bb = stg + s * B_SUB_B + (lane & 15) * B_ROW_B + khalf * 16;
            uint32_t b[4][4];
            #pragma unroll
            for (int p = 0; p < 4; ++p) ldsm_x4t(b[p], bb + p * 32);
            #pragma unroll
            for (int p = 0; p < 4; ++p) {                 // 8 independent accs
                mma16816(acc[2 * p],     a, b[p][0], b[p][1]);
                mma16816(acc[2 * p + 1], a, b[p][2], b[p][3]);
            }
        }

        // Epilogue at the end of each nc: +bias, ELU, 16-child reduce, store.
        if (kp == 31) {
            #pragma unroll
            for (int nt = 0; nt < 8; ++nt) {
                int col = nc * 64 + nt * 8 + (lane & 3) * 2;
                float b0 = bias[col], b1 = bias[col + 1];
                float s0 = elu(acc[nt][0] + b0) + elu(acc[nt][2] + b0);
                float s1 = elu(acc[nt][1] + b1) + elu(acc[nt][3] + b1);
                #pragma unroll
                for (int sh = 4; sh <= 16; sh <<= 1) {
                    s0 += __shfl_xor_sync(0xffffffffu, s0, sh);
                    s1 += __shfl_xor_sync(0xffffffffu, s1, sh);
                }
                if (lane < 4) {
                    g_hsum[(size_t)tree * H + col]     = s0;
                    g_hsum[(size_t)tree * H + col + 1] = s1;
                }
            }
        }
    }
}

// ---------------------------------------------------------------------------
// Stage 2: out[t][h] = elu( g_hsum[t][:] @ Wzf[:,h] + C * bzf[h] )
// ---------------------------------------------------------------------------
#define TB2 16
__global__ __launch_bounds__(256) void stage2_kernel(
    const float* __restrict__ Wzf,
    const float* __restrict__ bzf,
    float*       __restrict__ out)
{
    __shared__ float sh[TB2][H];
    const int b0 = blockIdx.x * TB2;
    const int tid = threadIdx.x;

    #pragma unroll
    for (int i = 0; i < (TB2 * H) / 256; ++i) {
        int e = tid + i * 256;
        sh[e >> 8][e & (H - 1)] = g_hsum[(size_t)(b0 + (e >> 8)) * H + (e & (H - 1))];
    }
    __syncthreads();

    const int h = tid;
    float acc[TB2];
    float binit = (float)C * bzf[h];
    #pragma unroll
    for (int r = 0; r < TB2; ++r) acc[r] = binit;

    #pragma unroll 4
    for (int j = 0; j < H; ++j) {
        float w = Wzf[(size_t)j * H + h];
        #pragma unroll
        for (int r = 0; r < TB2; ++r) acc[r] += sh[r][j] * w;
    }

    #pragma unroll
    for (int r = 0; r < TB2; ++r)
        out[(size_t)(b0 + r) * H + h] = elu(acc[r]);
}

// ---------------------------------------------------------------------------
// Launch: prep (Wz -> fp16) -> stage1 (mma.sync fp16) -> stage2
// ---------------------------------------------------------------------------
extern "C" void kernel_launch(void* const* d_in, const int* in_sizes, int n_in,
                              void* d_out, int out_size)
{
    const float* x        = (const float*)d_in[0];
    const float* Wz       = (const float*)d_in[1];
    const float* bz       = (const float*)d_in[2];
    const float* Wzf      = (const float*)d_in[3];
    const float* bzf      = (const float*)d_in[4];
    const int*   leaf_idx = (const int*)  d_in[5];

    const int T = in_sizes[5] / C;   // 8192

    cudaFuncSetAttribute(stage1_kernel,
                         cudaFuncAttributeMaxDynamicSharedMemorySize, SMEM_TOTAL);

    prep_kernel<<<KL * H * H / 256, 256>>>(Wz);
    stage1_kernel<<<T / TPB, 256, SMEM_TOTAL>>>(x, bz, leaf_idx);
    stage2_kernel<<<T / TB2, 256>>>(Wzf, bzf, (float*)d_out);
}

// round 6
// speedup vs baseline: 7.4700x; 1.2206x over previous
#include <cuda_runtime.h>
#include <cuda_fp16.h>
#include <cstdint>

#define H    256
#define KL   4
#define C    16
#define TMAX 8192
#define TPB  8          // trees per stage1 tile (= warps per block)

// ---------------------------------------------------------------------------
// Device scratch (no dynamic allocation allowed)
// ---------------------------------------------------------------------------
__device__ __half g_hsumh[TMAX * H];         // stage1 -> stage2, fp16
__device__ __half g_Bh[KL * H * H];          // Wz  fp16, layout [k][h][d]
__device__ __half g_Wfh[H * H];              // Wzf fp16, layout [j][d]

// ---------------------------------------------------------------------------
// Stage1 SMEM layout. Padded strides -> conflict-free ldmatrix.
// ---------------------------------------------------------------------------
#define OFF_BIAS   0
#define OFF_A      1024
#define A_ROW_B    528
#define A_TREE_B   (16 * A_ROW_B)                  // 8448
#define A_TOTAL    (TPB * A_TREE_B)                // 67584
#define OFF_B      (OFF_A + A_TOTAL)               // 68608
#define B_ROW_B    144
#define B_SUB_B    (16 * B_ROW_B)                  // 2304  (one k-step)
#define B_STAGE_B  (2 * B_SUB_B)                   // 4608  (two k-steps)
#define NSTAGE     3
#define SMEM_TOTAL (OFF_B + NSTAGE * B_STAGE_B)    // 82432 -> 2 blocks/SM

// Stage2 SMEM layout
#define S2M        32                              // trees per stage2 block
#define OFF2_BIAS  0
#define OFF2_A     1024
#define A2_SIZE    (S2M * A_ROW_B)                 // 16896
#define OFF2_B     (OFF2_A + A2_SIZE)              // 17920
#define B2_ROW_B   528
#define B2_STAGE   (16 * B2_ROW_B)                 // 8448
#define SMEM2      (OFF2_B + NSTAGE * B2_STAGE)    // 43264

// ---------------------------------------------------------------------------
// Helpers
// ---------------------------------------------------------------------------
__device__ __forceinline__ uint32_t smem_u32(const void* p) {
    uint32_t a;
    asm("{ .reg .u64 t; cvta.to.shared.u64 t, %1; cvt.u32.u64 %0, t; }" : "=r"(a) : "l"(p));
    return a;
}
__device__ __forceinline__ void cp16(uint32_t dst, const void* src) {
    uint64_t g;
    asm("cvta.to.global.u64 %0, %1;" : "=l"(g) : "l"(src));
    asm volatile("cp.async.cg.shared.global [%0], [%1], 16;" :: "r"(dst), "l"(g));
}
__device__ __forceinline__ void ldsm_x4(uint32_t (&r)[4], uint32_t addr) {
    asm volatile("ldmatrix.sync.aligned.m8n8.x4.shared.b16 {%0,%1,%2,%3}, [%4];"
                 : "=r"(r[0]), "=r"(r[1]), "=r"(r[2]), "=r"(r[3]) : "r"(addr));
}
__device__ __forceinline__ void ldsm_x4t(uint32_t (&r)[4], uint32_t addr) {
    asm volatile("ldmatrix.sync.aligned.m8n8.x4.trans.shared.b16 {%0,%1,%2,%3}, [%4];"
                 : "=r"(r[0]), "=r"(r[1]), "=r"(r[2]), "=r"(r[3]) : "r"(addr));
}
__device__ __forceinline__ void mma16816(float (&c)[4], const uint32_t (&a)[4],
                                         uint32_t b0, uint32_t b1) {
    asm volatile(
        "mma.sync.aligned.m16n8k16.row.col.f32.f16.f16.f32 "
        "{%0,%1,%2,%3}, {%4,%5,%6,%7}, {%8,%9}, {%0,%1,%2,%3};"
        : "+f"(c[0]), "+f"(c[1]), "+f"(c[2]), "+f"(c[3])
        : "r"(a[0]), "r"(a[1]), "r"(a[2]), "r"(a[3]), "r"(b0), "r"(b1));
}
__device__ __forceinline__ float elu(float v) { return (v > 0.0f) ? v : expm1f(v); }

// Copy one stage1 B stage: 2 k-steps = 32 h-rows x 64 d-cols fp16. 1 cp16/thread.
__device__ __forceinline__ void copyB(uint32_t dstStage, int nc, int kp, int tid) {
    const int kl = kp >> 3;
    const int h0 = (kp & 7) * 32;
    const int r  = tid >> 3;             // 0..31
    const int v8 = (tid & 7) * 8;        // 0..56
    const __half* src = g_Bh + (size_t)kl * 65536 + (size_t)(h0 + r) * 256 + nc * 64 + v8;
    cp16(dstStage + r * B_ROW_B + v8 * 2, src);
}

// Copy one stage2 B stage: k-step ks = 16 j-rows x 256 d-cols. 2 cp16/thread.
__device__ __forceinline__ void copyB2(uint32_t dstStage, int ks, int tid) {
    #pragma unroll
    for (int i = 0; i < 2; ++i) {
        int idx = tid + i * 256;          // 0..511
        int r   = idx >> 5;               // 0..15
        int v   = (idx & 31) * 16;        // byte offset in row (0..496)
        cp16(dstStage + r * B2_ROW_B + v,
             (const char*)g_Wfh + ((size_t)(ks * 16 + r) * 512 + v));
    }
}

// ---------------------------------------------------------------------------
// Prep: Wz -> fp16 (g_Bh) and Wzf -> fp16 (g_Wfh)
// ---------------------------------------------------------------------------
__global__ void prep_kernel(const float* __restrict__ Wz, const float* __restrict__ Wzf) {
    int idx = blockIdx.x * 256 + threadIdx.x;
    if (idx < KL * H * H) g_Bh[idx] = __float2half_rn(Wz[idx]);
    else                  g_Wfh[idx - KL * H * H] = __float2half_rn(Wzf[idx - KL * H * H]);
}

// ---------------------------------------------------------------------------
// Stage 1 (persistent): block strides tiles of 8 trees. Per tile: gather A,
// pipelined fp16 mma over (nc, k-steps) with roll baked into A-row addressing,
// epilogue: +bias, ELU, 16-child reduce -> g_hsumh (fp16).
// ---------------------------------------------------------------------------
__global__ __launch_bounds__(256, 2) void stage1_kernel(
    const float* __restrict__ x,
    const float* __restrict__ bz,
    const int*   __restrict__ leaf_idx,
    int ntiles)
{
    extern __shared__ char smem[];
    const uint32_t sb = smem_u32(smem);
    const int tid = threadIdx.x, wid = tid >> 5, lane = tid & 31;

    // bias[d] = sum_k bz[k][d]  (persists across tiles)
    ((float*)(smem + OFF_BIAS))[tid] = bz[tid] + bz[H + tid] + bz[2 * H + tid] + bz[3 * H + tid];

    const uint32_t aBase = sb + OFF_A + wid * A_TREE_B;
    const int rowlog = lane & 31 & 15;
    const int khalf  = lane >> 4;
    const float* bias = (const float*)(smem + OFF_BIAS);

    #pragma unroll 1
    for (int tile = blockIdx.x; tile < ntiles; tile += gridDim.x) {
        __syncthreads();   // previous tile fully done before smem reuse

        // Gather A: 128 rows (8 trees x 16 children) -> fp16; 2 threads/row.
        {
            int row = tid >> 1, half = tid & 1;
            int tree = tile * TPB + (row >> 4);
            int child = row & 15;
            int leaf = leaf_idx[tree * C + child];
            const float4* src = (const float4*)(x + (size_t)leaf * H + half * 128);
            char* dst = smem + OFF_A + (row >> 4) * A_TREE_B + child * A_ROW_B + half * 256;
            #pragma unroll
            for (int g = 0; g < 16; ++g) {
                float4 v0 = src[2 * g], v1 = src[2 * g + 1];
                __half2 h0 = __floats2half2_rn(v0.x, v0.y);
                __half2 h1 = __floats2half2_rn(v0.z, v0.w);
                __half2 h2 = __floats2half2_rn(v1.x, v1.y);
                __half2 h3 = __floats2half2_rn(v1.z, v1.w);
                *(uint4*)(dst + g * 16) = make_uint4(
                    *reinterpret_cast<uint32_t*>(&h0), *reinterpret_cast<uint32_t*>(&h1),
                    *reinterpret_cast<uint32_t*>(&h2), *reinterpret_cast<uint32_t*>(&h3));
            }
        }

        // Prime first two pipeline stages.
        copyB(sb + OFF_B + 0 * B_STAGE_B, 0, 0, tid);
        asm volatile("cp.async.commit_group;");
        copyB(sb + OFF_B + 1 * B_STAGE_B, 0, 1, tid);
        asm volatile("cp.async.commit_group;");

        __syncthreads();   // A gather visible to all warps

        const int tree = tile * TPB + wid;
        float acc[8][4];

        #pragma unroll 1
        for (int it = 0; it < 128; ++it) {
            const int nc = it >> 5, kp = it & 31, kl = kp >> 3;

            if (kp == 0) {
                #pragma unroll
                for (int nt = 0; nt < 8; ++nt)
                    #pragma unroll
                    for (int j = 0; j < 4; ++j) acc[nt][j] = 0.0f;
            }

            if (it + 2 < 128) {
                asm volatile("cp.async.wait_group 1;");
                __syncthreads();
                const int nit = it + 2;
                copyB(sb + OFF_B + (nit % NSTAGE) * B_STAGE_B, nit >> 5, nit & 31, tid);
                asm volatile("cp.async.commit_group;");
            } else {
                asm volatile("cp.async.wait_group 0;");
                __syncthreads();
            }

            const uint32_t stg = sb + OFF_B + (it % NSTAGE) * B_STAGE_B;
            const int rowp = (rowlog - kl) & 15;          // roll baked into A rows
            const uint32_t aRow = aBase + rowp * A_ROW_B + khalf * 16;

            #pragma unroll
            for (int s = 0; s < 2; ++s) {
                const int ks = (kp & 7) * 2 + s;

                uint32_t a[4];
                ldsm_x4(a, aRow + ks * 32);

                const uint32_t bb = stg + s * B_SUB_B + (lane & 15) * B_ROW_B + khalf * 16;
                uint32_t b[4][4];
                #pragma unroll
                for (int p = 0; p < 4; ++p) ldsm_x4t(b[p], bb + p * 32);
                #pragma unroll
                for (int p = 0; p < 4; ++p) {
                    mma16816(acc[2 * p],     a, b[p][0], b[p][1]);
                    mma16816(acc[2 * p + 1], a, b[p][2], b[p][3]);
                }
            }

            // Epilogue at the end of each nc: +bias, ELU, 16-child reduce.
            if (kp == 31) {
                #pragma unroll
                for (int nt = 0; nt < 8; ++nt) {
                    int col = nc * 64 + nt * 8 + (lane & 3) * 2;
                    float b0 = bias[col], b1 = bias[col + 1];
                    float s0 = elu(acc[nt][0] + b0) + elu(acc[nt][2] + b0);
                    float s1 = elu(acc[nt][1] + b1) + elu(acc[nt][3] + b1);
                    #pragma unroll
                    for (int sh = 4; sh <= 16; sh <<= 1) {
                        s0 += __shfl_xor_sync(0xffffffffu, s0, sh);
                        s1 += __shfl_xor_sync(0xffffffffu, s1, sh);
                    }
                    if (lane < 4) {
                        g_hsumh[(size_t)tree * H + col]     = __float2half_rn(s0);
                        g_hsumh[(size_t)tree * H + col + 1] = __float2half_rn(s1);
                    }
                }
            }
        }
    }
}

// ---------------------------------------------------------------------------
// Stage 2 (fp16 mma): out[t][:] = elu( hsum[t][:] @ Wzf + 16*bzf ).
// Block = 32 trees; warp (wr, wc) = m16 rows x n64 cols; 3-stage cp.async ring.
// ---------------------------------------------------------------------------
__global__ __launch_bounds__(256) void stage2_kernel(
    const float* __restrict__ bzf,
    float*       __restrict__ out)
{
    extern __shared__ char smem[];
    const uint32_t sb = smem_u32(smem);
    const int tid = threadIdx.x, wid = tid >> 5, lane = tid & 31;
    const int blk = blockIdx.x;

    // bias
    ((float*)(smem + OFF2_BIAS))[tid] = (float)C * bzf[tid];

    // A: 32 rows x 512B of g_hsumh, cp.async, 4 per thread.
    #pragma unroll
    for (int i = 0; i < 4; ++i) {
        int idx = tid + i * 256;
        int r = idx >> 5, v = (idx & 31) * 16;
        cp16(sb + OFF2_A + r * A_ROW_B + v,
             (const char*)g_hsumh + ((size_t)blk * S2M + r) * 512 + v);
    }
    // Prime B stages 0, 1 (A shares group 0 with B stage 0).
    copyB2(sb + OFF2_B + 0 * B2_STAGE, 0, tid);
    asm volatile("cp.async.commit_group;");
    copyB2(sb + OFF2_B + 1 * B2_STAGE, 1, tid);
    asm volatile("cp.async.commit_group;");

    __syncthreads();   // bias visibility

    const int wr = wid >> 2, wc = wid & 3;
    float acc[8][4];
    #pragma unroll
    for (int nt = 0; nt < 8; ++nt)
        #pragma unroll
        for (int j = 0; j < 4; ++j) acc[nt][j] = 0.0f;

    #pragma unroll 1
    for (int ks = 0; ks < 16; ++ks) {
        if (ks + 2 < 16) {
            asm volatile("cp.async.wait_group 1;");
            __syncthreads();
            copyB2(sb + OFF2_B + ((ks + 2) % NSTAGE) * B2_STAGE, ks + 2, tid);
            asm volatile("cp.async.commit_group;");
        } else {
            asm volatile("cp.async.wait_group 0;");
            __syncthreads();
        }

        const uint32_t stg = sb + OFF2_B + (ks % NSTAGE) * B2_STAGE;

        uint32_t a[4];
        ldsm_x4(a, sb + OFF2_A + (wr * 16 + (lane & 15)) * A_ROW_B + (lane >> 4) * 16 + ks * 32);

        const uint32_t bb = stg + (lane & 15) * B2_ROW_B + (lane >> 4) * 16 + wc * 128;
        uint32_t b[4][4];
        #pragma unroll
        for (int p = 0; p < 4; ++p) ldsm_x4t(b[p], bb + p * 32);
        #pragma unroll
        for (int p = 0; p < 4; ++p) {
            mma16816(acc[2 * p],     a, b[p][0], b[p][1]);
            mma16816(acc[2 * p + 1], a, b[p][2], b[p][3]);
        }
    }

    // Epilogue: +16*bzf, ELU, store.
    const float* biasp = (const float*)(smem + OFF2_BIAS);
    const int row0 = blk * S2M + wr * 16 + (lane >> 2);
    #pragma unroll
    for (int nt = 0; nt < 8; ++nt) {
        int col = wc * 64 + nt * 8 + (lane & 3) * 2;
        float b0 = biasp[col], b1 = biasp[col + 1];
        float2 v0 = make_float2(elu(acc[nt][0] + b0), elu(acc[nt][1] + b1));
        float2 v1 = make_float2(elu(acc[nt][2] + b0), elu(acc[nt][3] + b1));
        *(float2*)(out + (size_t)row0 * H + col)       = v0;
        *(float2*)(out + (size_t)(row0 + 8) * H + col) = v1;
    }
}

// ---------------------------------------------------------------------------
// Launch: prep -> stage1 (persistent, fp16 mma) -> stage2 (fp16 mma)
// ---------------------------------------------------------------------------
extern "C" void kernel_launch(void* const* d_in, const int* in_sizes, int n_in,
                              void* d_out, int out_size)
{
    const float* x        = (const float*)d_in[0];
    const float* Wz       = (const float*)d_in[1];
    const float* bz       = (const float*)d_in[2];
    const float* Wzf      = (const float*)d_in[3];
    const float* bzf      = (const float*)d_in[4];
    const int*   leaf_idx = (const int*)  d_in[5];

    const int T      = in_sizes[5] / C;   // 8192
    const int ntiles = T / TPB;           // 1024

    cudaFuncSetAttribute(stage1_kernel,
                         cudaFuncAttributeMaxDynamicSharedMemorySize, SMEM_TOTAL);
    cudaFuncSetAttribute(stage2_kernel,
                         cudaFuncAttributeMaxDynamicSharedMemorySize, SMEM2);

    prep_kernel<<<(KL * H * H + H * H) / 256, 256>>>(Wz, Wzf);

    int grid1 = 2 * 148;                  // 2 persistent blocks per SM
    if (grid1 > ntiles) grid1 = ntiles;
    stage1_kernel<<<grid1, 256, SMEM_TOTAL>>>(x, bz, leaf_idx, ntiles);

    stage2_kernel<<<T / S2M, 256, SMEM2>>>(bzf, (float*)d_out);
}

// round 7
// speedup vs baseline: 7.8676x; 1.0532x over previous
#include <cuda_runtime.h>
#include <cuda_fp16.h>
#include <cstdint>

#define H    256
#define KL   4
#define C    16
#define TMAX 8192
#define TPB  8          // trees per stage1 tile (= warps per block)

// ---------------------------------------------------------------------------
// Device scratch (no dynamic allocation allowed)
// ---------------------------------------------------------------------------
__device__ __half g_hsumh[TMAX * H];         // stage1 -> stage2, fp16
__device__ __half g_Bh[KL * H * H];          // Wz  fp16, layout [k][h][d]
__device__ __half g_Wfh[H * H];              // Wzf fp16, layout [j][d]

// ---------------------------------------------------------------------------
// Stage1 SMEM layout. Padded strides -> conflict-free ldmatrix.
// ---------------------------------------------------------------------------
#define OFF_BIAS   0
#define OFF_A      1024
#define A_ROW_B    528
#define A_TREE_B   (16 * A_ROW_B)                  // 8448
#define A_TOTAL    (TPB * A_TREE_B)                // 67584
#define OFF_B      (OFF_A + A_TOTAL)               // 68608
#define B_ROW_B    144
#define B_SUB_B    (16 * B_ROW_B)                  // 2304  (one k-step)
#define B_STAGE_B  (4 * B_SUB_B)                   // 9216  (four k-steps)
#define NSTAGE     3
#define SMEM_TOTAL (OFF_B + NSTAGE * B_STAGE_B)    // 96256 -> 2 blocks/SM

// Stage2 SMEM layout
#define S2M        32                              // trees per stage2 block
#define OFF2_BIAS  0
#define OFF2_A     1024
#define A2_SIZE    (S2M * A_ROW_B)                 // 16896
#define OFF2_B     (OFF2_A + A2_SIZE)              // 17920
#define B2_ROW_B   528
#define B2_STAGE   (16 * B2_ROW_B)                 // 8448
#define SMEM2      (OFF2_B + NSTAGE * B2_STAGE)    // 43264

// ---------------------------------------------------------------------------
// Helpers
// ---------------------------------------------------------------------------
__device__ __forceinline__ uint32_t smem_u32(const void* p) {
    uint32_t a;
    asm("{ .reg .u64 t; cvta.to.shared.u64 t, %1; cvt.u32.u64 %0, t; }" : "=r"(a) : "l"(p));
    return a;
}
__device__ __forceinline__ void cp16(uint32_t dst, const void* src) {
    uint64_t g;
    asm("cvta.to.global.u64 %0, %1;" : "=l"(g) : "l"(src));
    asm volatile("cp.async.cg.shared.global [%0], [%1], 16;" :: "r"(dst), "l"(g));
}
__device__ __forceinline__ void ldsm_x4(uint32_t (&r)[4], uint32_t addr) {
    asm volatile("ldmatrix.sync.aligned.m8n8.x4.shared.b16 {%0,%1,%2,%3}, [%4];"
                 : "=r"(r[0]), "=r"(r[1]), "=r"(r[2]), "=r"(r[3]) : "r"(addr));
}
__device__ __forceinline__ void ldsm_x4t(uint32_t (&r)[4], uint32_t addr) {
    asm volatile("ldmatrix.sync.aligned.m8n8.x4.trans.shared.b16 {%0,%1,%2,%3}, [%4];"
                 : "=r"(r[0]), "=r"(r[1]), "=r"(r[2]), "=r"(r[3]) : "r"(addr));
}
__device__ __forceinline__ void mma16816(float (&c)[4], const uint32_t (&a)[4],
                                         uint32_t b0, uint32_t b1) {
    asm volatile(
        "mma.sync.aligned.m16n8k16.row.col.f32.f16.f16.f32 "
        "{%0,%1,%2,%3}, {%4,%5,%6,%7}, {%8,%9}, {%0,%1,%2,%3};"
        : "+f"(c[0]), "+f"(c[1]), "+f"(c[2]), "+f"(c[3])
        : "r"(a[0]), "r"(a[1]), "r"(a[2]), "r"(a[3]), "r"(b0), "r"(b1));
}
__device__ __forceinline__ float elu(float v) { return (v > 0.0f) ? v : expm1f(v); }

// Copy one stage1 B stage: 4 k-steps = 64 h-rows x 64 d-cols fp16. 2 cp16/thread.
// kp4 in 0..15 indexes 4-kstep groups within one nc: kl = kp4>>2, rows (kp4&3)*64.
__device__ __forceinline__ void copyB(uint32_t dstStage, int nc, int kp4, int tid) {
    const int kl = kp4 >> 2;
    const int h0 = (kp4 & 3) * 64;
    #pragma unroll
    for (int i = 0; i < 2; ++i) {
        int idx = tid + i * 256;          // 0..511
        int r   = idx >> 3;               // 0..63
        int v8  = (idx & 7) * 8;          // 0..56
        const __half* src = g_Bh + (size_t)kl * 65536 + (size_t)(h0 + r) * 256 + nc * 64 + v8;
        cp16(dstStage + r * B_ROW_B + v8 * 2, src);
    }
}

// Copy one stage2 B stage: k-step ks = 16 j-rows x 256 d-cols. 2 cp16/thread.
__device__ __forceinline__ void copyB2(uint32_t dstStage, int ks, int tid) {
    #pragma unroll
    for (int i = 0; i < 2; ++i) {
        int idx = tid + i * 256;          // 0..511
        int r   = idx >> 5;               // 0..15
        int v   = (idx & 31) * 16;        // byte offset in row (0..496)
        cp16(dstStage + r * B2_ROW_B + v,
             (const char*)g_Wfh + ((size_t)(ks * 16 + r) * 512 + v));
    }
}

// ---------------------------------------------------------------------------
// Prep: Wz -> fp16 (g_Bh) and Wzf -> fp16 (g_Wfh)
// ---------------------------------------------------------------------------
__global__ void prep_kernel(const float* __restrict__ Wz, const float* __restrict__ Wzf) {
    int idx = blockIdx.x * 256 + threadIdx.x;
    if (idx < KL * H * H) g_Bh[idx] = __float2half_rn(Wz[idx]);
    else                  g_Wfh[idx - KL * H * H] = __float2half_rn(Wzf[idx - KL * H * H]);
}

// ---------------------------------------------------------------------------
// Stage 1 (persistent): block strides tiles of 8 trees. Per tile: prime B ring,
// gather A (overlapped with B DMA), pipelined fp16 mma over (nc, k-steps) with
// the roll baked into A-row addressing; epilogue: +bias, ELU, 16-child reduce.
// 64 iterations/tile, ONE __syncthreads per iteration (4 k-steps each).
// ---------------------------------------------------------------------------
__global__ __launch_bounds__(256, 2) void stage1_kernel(
    const float* __restrict__ x,
    const float* __restrict__ bz,
    const int*   __restrict__ leaf_idx,
    int ntiles)
{
    extern __shared__ char smem[];
    const uint32_t sb = smem_u32(smem);
    const int tid = threadIdx.x, wid = tid >> 5, lane = tid & 31;

    // bias[d] = sum_k bz[k][d]  (persists across tiles)
    ((float*)(smem + OFF_BIAS))[tid] = bz[tid] + bz[H + tid] + bz[2 * H + tid] + bz[3 * H + tid];

    const uint32_t aBase = sb + OFF_A + wid * A_TREE_B;
    const int rowlog = lane & 15;
    const int khalf  = lane >> 4;
    const float* bias = (const float*)(smem + OFF_BIAS);

    #pragma unroll 1
    for (int tile = blockIdx.x; tile < ntiles; tile += gridDim.x) {
        __syncthreads();   // previous tile fully done before smem reuse

        // Prime first two B pipeline stages FIRST (DMA overlaps the gather below).
        copyB(sb + OFF_B + 0 * B_STAGE_B, 0, 0, tid);
        asm volatile("cp.async.commit_group;");
        copyB(sb + OFF_B + 1 * B_STAGE_B, 0, 1, tid);
        asm volatile("cp.async.commit_group;");

        // Gather A: 128 rows (8 trees x 16 children) -> fp16; 2 threads/row.
        {
            int row = tid >> 1, half = tid & 1;
            int tree = tile * TPB + (row >> 4);
            int child = row & 15;
            int leaf = leaf_idx[tree * C + child];
            const float4* src = (const float4*)(x + (size_t)leaf * H + half * 128);
            char* dst = smem + OFF_A + (row >> 4) * A_TREE_B + child * A_ROW_B + half * 256;
            #pragma unroll
            for (int g = 0; g < 16; ++g) {
                float4 v0 = src[2 * g], v1 = src[2 * g + 1];
                __half2 h0 = __floats2half2_rn(v0.x, v0.y);
                __half2 h1 = __floats2half2_rn(v0.z, v0.w);
                __half2 h2 = __floats2half2_rn(v1.x, v1.y);
                __half2 h3 = __floats2half2_rn(v1.z, v1.w);
                *(uint4*)(dst + g * 16) = make_uint4(
                    *reinterpret_cast<uint32_t*>(&h0), *reinterpret_cast<uint32_t*>(&h1),
                    *reinterpret_cast<uint32_t*>(&h2), *reinterpret_cast<uint32_t*>(&h3));
            }
        }

        __syncthreads();   // A gather visible to all warps

        const int tree = tile * TPB + wid;
        float acc[8][4];

        #pragma unroll 1
        for (int it = 0; it < 64; ++it) {
            const int nc = it >> 4, kp = it & 15, kl = kp >> 2;

            if (kp == 0) {
                #pragma unroll
                for (int nt = 0; nt < 8; ++nt)
                    #pragma unroll
                    for (int j = 0; j < 4; ++j) acc[nt][j] = 0.0f;
            }

            if (it + 2 < 64) {
                asm volatile("cp.async.wait_group 1;");
                __syncthreads();
                const int nit = it + 2;
                copyB(sb + OFF_B + (nit % NSTAGE) * B_STAGE_B, nit >> 4, nit & 15, tid);
                asm volatile("cp.async.commit_group;");
            } else {
                asm volatile("cp.async.wait_group 0;");
                __syncthreads();
            }

            const uint32_t stg = sb + OFF_B + (it % NSTAGE) * B_STAGE_B;
            const int rowp = (rowlog - kl) & 15;          // roll baked into A rows
            const uint32_t aRow = aBase + rowp * A_ROW_B + khalf * 16;

            #pragma unroll
            for (int s = 0; s < 4; ++s) {                 // four k-steps per stage
                const int ks = (kp & 3) * 4 + s;

                uint32_t a[4];
                ldsm_x4(a, aRow + ks * 32);

                const uint32_t bb = stg + s * B_SUB_B + (lane & 15) * B_ROW_B + khalf * 16;
                uint32_t b[4][4];
                #pragma unroll
                for (int p = 0; p < 4; ++p) ldsm_x4t(b[p], bb + p * 32);
                #pragma unroll
                for (int p = 0; p < 4; ++p) {
                    mma16816(acc[2 * p],     a, b[p][0], b[p][1]);
                    mma16816(acc[2 * p + 1], a, b[p][2], b[p][3]);
                }
            }

            // Epilogue at the end of each nc: +bias, ELU, 16-child reduce.
            if (kp == 15) {
                #pragma unroll
                for (int nt = 0; nt < 8; ++nt) {
                    int col = nc * 64 + nt * 8 + (lane & 3) * 2;
                    float b0 = bias[col], b1 = bias[col + 1];
                    float s0 = elu(acc[nt][0] + b0) + elu(acc[nt][2] + b0);
                    float s1 = elu(acc[nt][1] + b1) + elu(acc[nt][3] + b1);
                    #pragma unroll
                    for (int sh = 4; sh <= 16; sh <<= 1) {
                        s0 += __shfl_xor_sync(0xffffffffu, s0, sh);
                        s1 += __shfl_xor_sync(0xffffffffu, s1, sh);
                    }
                    if (lane < 4) {
                        g_hsumh[(size_t)tree * H + col]     = __float2half_rn(s0);
                        g_hsumh[(size_t)tree * H + col + 1] = __float2half_rn(s1);
                    }
                }
            }
        }
    }
}

// ---------------------------------------------------------------------------
// Stage 2 (fp16 mma): out[t][:] = elu( hsum[t][:] @ Wzf + 16*bzf ).
// Block = 32 trees; warp (wr, wc) = m16 rows x n64 cols; 3-stage cp.async ring.
// ---------------------------------------------------------------------------
__global__ __launch_bounds__(256) void stage2_kernel(
    const float* __restrict__ bzf,
    float*       __restrict__ out)
{
    extern __shared__ char smem[];
    const uint32_t sb = smem_u32(smem);
    const int tid = threadIdx.x, wid = tid >> 5, lane = tid & 31;
    const int blk = blockIdx.x;

    // bias
    ((float*)(smem + OFF2_BIAS))[tid] = (float)C * bzf[tid];

    // A: 32 rows x 512B of g_hsumh, cp.async, 4 per thread.
    #pragma unroll
    for (int i = 0; i < 4; ++i) {
        int idx = tid + i * 256;
        int r = idx >> 5, v = (idx & 31) * 16;
        cp16(sb + OFF2_A + r * A_ROW_B + v,
             (const char*)g_hsumh + ((size_t)blk * S2M + r) * 512 + v);
    }
    // Prime B stages 0, 1 (A shares group 0 with B stage 0).
    copyB2(sb + OFF2_B + 0 * B2_STAGE, 0, tid);
    asm volatile("cp.async.commit_group;");
    copyB2(sb + OFF2_B + 1 * B2_STAGE, 1, tid);
    asm volatile("cp.async.commit_group;");

    __syncthreads();   // bias visibility

    const int wr = wid >> 2, wc = wid & 3;
    float acc[8][4];
    #pragma unroll
    for (int nt = 0; nt < 8; ++nt)
        #pragma unroll
        for (int j = 0; j < 4; ++j) acc[nt][j] = 0.0f;

    #pragma unroll 1
    for (int ks = 0; ks < 16; ++ks) {
        if (ks + 2 < 16) {
            asm volatile("cp.async.wait_group 1;");
            __syncthreads();
            copyB2(sb + OFF2_B + ((ks + 2) % NSTAGE) * B2_STAGE, ks + 2, tid);
            asm volatile("cp.async.commit_group;");
        } else {
            asm volatile("cp.async.wait_group 0;");
            __syncthreads();
        }

        const uint32_t stg = sb + OFF2_B + (ks % NSTAGE) * B2_STAGE;

        uint32_t a[4];
        ldsm_x4(a, sb + OFF2_A + (wr * 16 + (lane & 15)) * A_ROW_B + (lane >> 4) * 16 + ks * 32);

        const uint32_t bb = stg + (lane & 15) * B2_ROW_B + (lane >> 4) * 16 + wc * 128;
        uint32_t b[4][4];
        #pragma unroll
        for (int p = 0; p < 4; ++p) ldsm_x4t(b[p], bb + p * 32);
        #pragma unroll
        for (int p = 0; p < 4; ++p) {
            mma16816(acc[2 * p],     a, b[p][0], b[p][1]);
            mma16816(acc[2 * p + 1], a, b[p][2], b[p][3]);
        }
    }

    // Epilogue: +16*bzf, ELU, store.
    const float* biasp = (const float*)(smem + OFF2_BIAS);
    const int row0 = blk * S2M + wr * 16 + (lane >> 2);
    #pragma unroll
    for (int nt = 0; nt < 8; ++nt) {
        int col = wc * 64 + nt * 8 + (lane & 3) * 2;
        float b0 = biasp[col], b1 = biasp[col + 1];
        float2 v0 = make_float2(elu(acc[nt][0] + b0), elu(acc[nt][1] + b1));
        float2 v1 = make_float2(elu(acc[nt][2] + b0), elu(acc[nt][3] + b1));
        *(float2*)(out + (size_t)row0 * H + col)       = v0;
        *(float2*)(out + (size_t)(row0 + 8) * H + col) = v1;
    }
}

// ---------------------------------------------------------------------------
// Launch: prep -> stage1 (persistent, fp16 mma) -> stage2 (fp16 mma)
// ---------------------------------------------------------------------------
extern "C" void kernel_launch(void* const* d_in, const int* in_sizes, int n_in,
                              void* d_out, int out_size)
{
    const float* x        = (const float*)d_in[0];
    const float* Wz       = (const float*)d_in[1];
    const float* bz       = (const float*)d_in[2];
    const float* Wzf      = (const float*)d_in[3];
    const float* bzf      = (const float*)d_in[4];
    const int*   leaf_idx = (const int*)  d_in[5];

    const int T      = in_sizes[5] / C;   // 8192
    const int ntiles = T / TPB;           // 1024

    cudaFuncSetAttribute(stage1_kernel,
                         cudaFuncAttributeMaxDynamicSharedMemorySize, SMEM_TOTAL);
    cudaFuncSetAttribute(stage2_kernel,
                         cudaFuncAttributeMaxDynamicSharedMemorySize, SMEM2);

    prep_kernel<<<(KL * H * H + H * H) / 256, 256>>>(Wz, Wzf);

    int grid1 = 2 * 148;                  // 2 persistent blocks per SM
    if (grid1 > ntiles) grid1 = ntiles;
    stage1_kernel<<<grid1, 256, SMEM_TOTAL>>>(x, bz, leaf_idx, ntiles);

    stage2_kernel<<<T / S2M, 256, SMEM2>>>(bzf, (float*)d_out);
}